// round 16
// baseline (speedup 1.0000x reference)
#include <cuda_runtime.h>
#include <cuda_fp16.h>
#include <mma.h>
#include <cstdint>

using namespace nvcuda;

// Problem constants
#define SEQ   2048
#define HDIM  2880
#define NH    64
#define HD    64
#define NKV   8
#define RANK  384
#define QDIM  4096   // NH*HD
#define KVDIM 1024   // NKV*HD*2
#define ROPE_BASE 150000.0f

// ---------------------------------------------------------------------------
// Scratch
// ---------------------------------------------------------------------------
__device__ float  g_q   [SEQ * QDIM];
__device__ float  g_ckv [SEQ * RANK];
__device__ __half g_ckvh[SEQ * RANK];
__device__ float  g_kv  [SEQ * KVDIM];
__device__ __half g_qt  [NH  * SEQ * HD];
__device__ __half g_kt  [NKV * SEQ * HD];
__device__ __half g_vtT [NKV * HD * SEQ];
__device__ __half g_attn[SEQ * QDIM];
__device__ __half g_h   [SEQ * HDIM];
__device__ __half g_qw  [QDIM * HDIM];
__device__ __half g_kaw [RANK * HDIM];
__device__ __half g_kbw [KVDIM * RANK];
__device__ __half g_ow  [HDIM * QDIM];

__device__ __forceinline__ uint32_t smem_u32(const void* p) {
    uint32_t a;
    asm("{ .reg .u64 t; cvta.to.shared.u64 t, %1; cvt.u32.u64 %0, t; }"
        : "=r"(a) : "l"(p));
    return a;
}
__device__ __forceinline__ void cp_async16(uint32_t dst, const void* src) {
    asm volatile("cp.async.ca.shared.global [%0], [%1], 16;"
                 :: "r"(dst), "l"(src) : "memory");
}
__device__ __forceinline__ void cp_async_commit() {
    asm volatile("cp.async.commit_group;" ::: "memory");
}
__device__ __forceinline__ void cp_async_wait1() {
    asm volatile("cp.async.wait_group 1;" ::: "memory");
}
__device__ __forceinline__ void cp_async_wait0() {
    asm volatile("cp.async.wait_group 0;" ::: "memory");
}
__device__ __forceinline__ uint32_t pack_h2(float x, float y) {
    __half2 h = __float22half2_rn(make_float2(x, y));
    return *reinterpret_cast<uint32_t*>(&h);
}

// mma.sync m16n8k16 fp16 -> f32 accum
__device__ __forceinline__ void mma_f16(float d[4], const uint32_t a[4],
                                        const uint32_t b[2]) {
    asm volatile(
        "mma.sync.aligned.m16n8k16.row.col.f32.f16.f16.f32 "
        "{%0,%1,%2,%3},{%4,%5,%6,%7},{%8,%9},{%0,%1,%2,%3};"
        : "+f"(d[0]), "+f"(d[1]), "+f"(d[2]), "+f"(d[3])
        : "r"(a[0]), "r"(a[1]), "r"(a[2]), "r"(a[3]),
          "r"(b[0]), "r"(b[1]));
}

// ---------------------------------------------------------------------------
// Elementwise fp16 rounding pass
// ---------------------------------------------------------------------------
__global__ void round_half_kernel(const float* __restrict__ in,
                                  __half* __restrict__ out, int n4) {
    int i = blockIdx.x * blockDim.x + threadIdx.x;
    if (i < n4) {
        float4 v = ((const float4*)in)[i];
        uint2 u;
        u.x = pack_h2(v.x, v.y);
        u.y = pack_h2(v.z, v.w);
        ((uint2*)out)[i] = u;
    }
}

// ---------------------------------------------------------------------------
// Pipelined FP16 wmma GEMM: C = A @ B^T, f32 out. (R11 winner, unchanged)
// ---------------------------------------------------------------------------
#define GLDT 40
#define GST_A (128 * GLDT)
#define GST_HALVES ((128 + 128) * GLDT)
#define GSTAGES 3
#define GSMEM_BYTES (GSTAGES * GST_HALVES * 2)   // 61440

__global__ __launch_bounds__(256, 2)
void wgemm_fp16(const __half* __restrict__ A, const __half* __restrict__ B,
                float* __restrict__ C, int M, int N, int K) {
    extern __shared__ __half smh[];
    const int tid  = threadIdx.x;
    const int warp = tid >> 5;
    const int wm   = warp >> 2;
    const int wn   = warp & 3;
    const int row0 = blockIdx.y * 128;
    const int col0 = blockIdx.x * 128;
    const int NC   = K >> 5;

    wmma::fragment<wmma::accumulator, 16, 16, 16, float> acc[4][2];
#pragma unroll
    for (int i = 0; i < 4; i++)
#pragma unroll
        for (int j = 0; j < 2; j++) wmma::fill_fragment(acc[i][j], 0.0f);

    auto issue = [&](int c) {
        __half* sa = smh + (c % GSTAGES) * GST_HALVES;
        __half* sb = sa + GST_A;
        const int k0 = c << 5;
#pragma unroll
        for (int i = 0; i < 2; i++) {
            int idx = tid + i * 256;
            int r = idx >> 2, c8 = (idx & 3) * 8;
            cp_async16(smem_u32(sa + r * GLDT + c8),
                       A + (size_t)(row0 + r) * K + k0 + c8);
        }
#pragma unroll
        for (int i = 0; i < 2; i++) {
            int idx = tid + i * 256;
            int r = idx >> 2, c8 = (idx & 3) * 8;
            int gn = col0 + r; if (gn >= N) gn = N - 1;
            cp_async16(smem_u32(sb + r * GLDT + c8),
                       B + (size_t)gn * K + k0 + c8);
        }
    };

#pragma unroll
    for (int s = 0; s < GSTAGES - 1; s++) {
        issue(s);
        cp_async_commit();
    }

    for (int c = 0; c < NC; c++) {
        cp_async_wait1();
        __syncthreads();
        if (c + GSTAGES - 1 < NC) issue(c + GSTAGES - 1);
        cp_async_commit();

        __half* sa = smh + (c % GSTAGES) * GST_HALVES;
        __half* sb = sa + GST_A;
#pragma unroll
        for (int kk = 0; kk < 32; kk += 16) {
            wmma::fragment<wmma::matrix_a, 16, 16, 16, __half, wmma::row_major> af[4];
            wmma::fragment<wmma::matrix_b, 16, 16, 16, __half, wmma::col_major> bf[2];
#pragma unroll
            for (int i = 0; i < 4; i++)
                wmma::load_matrix_sync(af[i], sa + (wm * 64 + i * 16) * GLDT + kk, GLDT);
#pragma unroll
            for (int j = 0; j < 2; j++)
                wmma::load_matrix_sync(bf[j], sb + (wn * 32 + j * 16) * GLDT + kk, GLDT);
#pragma unroll
            for (int i = 0; i < 4; i++)
#pragma unroll
                for (int j = 0; j < 2; j++)
                    wmma::mma_sync(acc[i][j], af[i], bf[j], acc[i][j]);
        }
        __syncthreads();
    }

#pragma unroll
    for (int i = 0; i < 4; i++) {
        int gm = row0 + wm * 64 + i * 16;
#pragma unroll
        for (int j = 0; j < 2; j++) {
            int gn = col0 + wn * 32 + j * 16;
            if (gn < N)
                wmma::store_matrix_sync(C + (size_t)gm * N + gn, acc[i][j], N,
                                        wmma::mem_row_major);
        }
    }
}

// ---------------------------------------------------------------------------
// RoPE — fp16 outputs
// ---------------------------------------------------------------------------
__device__ __forceinline__ void rope_cs(int s, int d, float& c, float& sn) {
    int dd = d & 31;
    float inv = 1.0f / powf(ROPE_BASE, (float)(2 * dd) / 64.0f);
    float ang = (float)s * inv;
    c = cosf(ang);
    sn = sinf(ang);
}

__global__ void rope_q_kernel(const float* __restrict__ q, const float* __restrict__ qb,
                              __half* __restrict__ qt) {
    int s = blockIdx.x;
    int t = threadIdx.x;
    int h = blockIdx.y * 4 + (t >> 6);
    int d = t & 63;
    const float* row = q + (size_t)s * QDIM + h * HD;
    const float* brow = qb + h * HD;
    float v = row[d] + brow[d];
    float other = (d < 32) ? -(row[d + 32] + brow[d + 32]) : (row[d - 32] + brow[d - 32]);
    float c, sn; rope_cs(s, d, c, sn);
    qt[((size_t)h * SEQ + s) * HD + d] = __float2half_rn(v * c + other * sn);
}

__global__ void rope_kv_kernel(const float* __restrict__ kv,
                               __half* __restrict__ kt, __half* __restrict__ vtT) {
    __shared__ float vs[64][65];
    const int s0 = blockIdx.x * 64;
    const int kh = blockIdx.y;
    const int tid = threadIdx.x;

#pragma unroll
    for (int it = 0; it < 16; it++) {
        int r = it * 4 + (tid >> 6);
        int d = tid & 63;
        int s = s0 + r;
        const float* row = kv + (size_t)s * KVDIM + kh * (2 * HD);
        float kval = row[d];
        float other = (d < 32) ? -row[d + 32] : row[d - 32];
        float c, sn; rope_cs(s, d, c, sn);
        kt[((size_t)kh * SEQ + s) * HD + d] = __float2half_rn(kval * c + other * sn);
        vs[r][d] = row[HD + d];
    }
    __syncthreads();
#pragma unroll
    for (int it = 0; it < 16; it++) {
        int d = it * 4 + (tid >> 6);
        int cc = tid & 63;
        vtT[((size_t)kh * HD + d) * SEQ + s0 + cc] = __float2half_rn(vs[cc][d]);
    }
}

// ---------------------------------------------------------------------------
// Flash attention fp16 (R15 kernel, unchanged)
// ---------------------------------------------------------------------------
#define KLD 72
#define ABUF (2 * 64 * KLD)
#define ASMEM_BYTES (2 * ABUF * 2)          // 36864

__global__ __launch_bounds__(256, 2)
void attn_fp16(const __half* __restrict__ qt, const __half* __restrict__ kt,
               const __half* __restrict__ vtT, __half* __restrict__ out, int qb0) {
    extern __shared__ __half smh[];
    const int tid  = threadIdx.x;
    const int warp = tid >> 5;
    const int lane = tid & 31;
    const int gid  = lane >> 2;
    const int q4   = lane & 3;
    const int h    = blockIdx.y;
    const int qb   = qb0 + gridDim.x - 1 - blockIdx.x;
    const int kvh  = h >> 3;

    const __half* Qg = qt + ((size_t)h * SEQ + qb * 128) * HD;
    const __half* Kg = kt + (size_t)kvh * SEQ * HD;
    const __half* Vg = vtT + (size_t)kvh * HD * SEQ;

#pragma unroll
    for (int i = 0; i < 4; i++) {
        int idx = tid + i * 256;
        int r = idx >> 3, c8 = (idx & 7) * 8;
        cp_async16(smem_u32(smh + r * KLD + c8), Qg + r * 64 + c8);
    }
    cp_async_commit();
    cp_async_wait0();
    __syncthreads();

    uint32_t qa[4][4];
    {
        const __half* qrow = smh + (warp * 16 + gid) * KLD;
#pragma unroll
        for (int kk = 0; kk < 4; kk++) {
            qa[kk][0] = *(const uint32_t*)&qrow[kk * 16 + 2 * q4];
            qa[kk][1] = *(const uint32_t*)&qrow[8 * KLD + kk * 16 + 2 * q4];
            qa[kk][2] = *(const uint32_t*)&qrow[kk * 16 + 8 + 2 * q4];
            qa[kk][3] = *(const uint32_t*)&qrow[8 * KLD + kk * 16 + 8 + 2 * q4];
        }
    }
    __syncthreads();

    auto issue_kv = [&](int jt, int buf) {
        __half* kb = smh + buf * ABUF;
        __half* vb = kb + 64 * KLD;
#pragma unroll
        for (int i = 0; i < 2; i++) {
            int idx = tid + i * 256;
            int r = idx >> 3, c8 = (idx & 7) * 8;
            cp_async16(smem_u32(kb + r * KLD + c8),
                       Kg + ((size_t)jt * 64 + r) * 64 + c8);
            cp_async16(smem_u32(vb + r * KLD + c8),
                       Vg + (size_t)r * SEQ + jt * 64 + c8);
        }
    };

    issue_kv(0, 0);
    cp_async_commit();

    const int ntiles = 2 * qb + 2;
    const int i0     = qb * 128 + warp * 16 + gid;
    const int iwmax  = qb * 128 + warp * 16 + 15;

    float m0 = -3.0e38f, m1 = -3.0e38f, l0 = 0.f, l1 = 0.f;
    float O[8][4];
#pragma unroll
    for (int t = 0; t < 8; t++)
#pragma unroll
        for (int e = 0; e < 4; e++) O[t][e] = 0.f;

    const uint32_t FULL = 0xffffffffu;

    for (int jt = 0; jt < ntiles; jt++) {
        const int buf = jt & 1;
        if (jt + 1 < ntiles) issue_kv(jt + 1, buf ^ 1);
        cp_async_commit();
        cp_async_wait1();
        __syncthreads();

        if (jt * 64 <= iwmax) {
            const __half* Kb = smh + buf * ABUF;
            const __half* Vb = Kb + 64 * KLD;

            float st[8][4];
#pragma unroll
            for (int t = 0; t < 8; t++)
#pragma unroll
                for (int e = 0; e < 4; e++) st[t][e] = 0.f;

#pragma unroll
            for (int kk = 0; kk < 4; kk++) {
#pragma unroll
                for (int t = 0; t < 8; t++) {
                    const __half* kp = Kb + (t * 8 + gid) * KLD + kk * 16 + 2 * q4;
                    uint32_t b[2] = { *(const uint32_t*)kp, *(const uint32_t*)(kp + 8) };
                    mma_f16(st[t], qa[kk], b);
                }
            }

            float mx0 = -3.0e38f, mx1 = -3.0e38f;
            const int jb2 = jt * 64 + 2 * q4;
#pragma unroll
            for (int t = 0; t < 8; t++) {
#pragma unroll
                for (int e = 0; e < 2; e++) {
                    int j = jb2 + t * 8 + e;
                    float v0 = st[t][e] * 0.125f;
                    float v1 = st[t][2 + e] * 0.125f;
                    if (j > i0)     v0 = -3.0e38f;
                    if (j > i0 + 8) v1 = -3.0e38f;
                    st[t][e] = v0; st[t][2 + e] = v1;
                    mx0 = fmaxf(mx0, v0); mx1 = fmaxf(mx1, v1);
                }
            }
            mx0 = fmaxf(mx0, __shfl_xor_sync(FULL, mx0, 1));
            mx0 = fmaxf(mx0, __shfl_xor_sync(FULL, mx0, 2));
            mx1 = fmaxf(mx1, __shfl_xor_sync(FULL, mx1, 1));
            mx1 = fmaxf(mx1, __shfl_xor_sync(FULL, mx1, 2));

            float mn0 = fmaxf(m0, mx0), mn1 = fmaxf(m1, mx1);
            float sc0 = __expf(m0 - mn0), sc1 = __expf(m1 - mn1);
            m0 = mn0; m1 = mn1;

            float rs0 = 0.f, rs1 = 0.f;
#pragma unroll
            for (int t = 0; t < 8; t++) {
#pragma unroll
                for (int e = 0; e < 2; e++) {
                    float p0 = __expf(st[t][e]     - m0);
                    float p1 = __expf(st[t][2 + e] - m1);
                    st[t][e] = p0; st[t][2 + e] = p1;
                    rs0 += p0; rs1 += p1;
                }
            }

#pragma unroll
            for (int t = 0; t < 8; t++) {
                O[t][0] *= sc0; O[t][1] *= sc0;
                O[t][2] *= sc1; O[t][3] *= sc1;
            }

            uint32_t pa[4][4];
#pragma unroll
            for (int kk = 0; kk < 4; kk++) {
                pa[kk][0] = pack_h2(st[2 * kk][0],     st[2 * kk][1]);
                pa[kk][1] = pack_h2(st[2 * kk][2],     st[2 * kk][3]);
                pa[kk][2] = pack_h2(st[2 * kk + 1][0], st[2 * kk + 1][1]);
                pa[kk][3] = pack_h2(st[2 * kk + 1][2], st[2 * kk + 1][3]);
            }

#pragma unroll
            for (int kk = 0; kk < 4; kk++) {
#pragma unroll
                for (int t = 0; t < 8; t++) {
                    const __half* vp = Vb + (t * 8 + gid) * KLD + kk * 16 + 2 * q4;
                    uint32_t b[2] = { *(const uint32_t*)vp, *(const uint32_t*)(vp + 8) };
                    mma_f16(O[t], pa[kk], b);
                }
            }

            rs0 += __shfl_xor_sync(FULL, rs0, 1);
            rs0 += __shfl_xor_sync(FULL, rs0, 2);
            rs1 += __shfl_xor_sync(FULL, rs1, 1);
            rs1 += __shfl_xor_sync(FULL, rs1, 2);
            l0 = l0 * sc0 + rs0;
            l1 = l1 * sc1 + rs1;
        }
        __syncthreads();
    }

    float inv0 = 1.0f / l0, inv1 = 1.0f / l1;
    const int r0 = qb * 128 + warp * 16 + gid;
    __half* dst0 = out + (size_t)r0 * QDIM + h * HD;
    __half* dst1 = dst0 + (size_t)8 * QDIM;
#pragma unroll
    for (int t = 0; t < 8; t++) {
        uint32_t v0 = pack_h2(O[t][0] * inv0, O[t][1] * inv0);
        uint32_t v1 = pack_h2(O[t][2] * inv1, O[t][3] * inv1);
        *(uint32_t*)(dst0 + t * 8 + 2 * q4) = v0;
        *(uint32_t*)(dst1 + t * 8 + 2 * q4) = v1;
    }
}

// ---------------------------------------------------------------------------
// Bias add (operates on a row range via pointer offset)
// ---------------------------------------------------------------------------
__global__ void add_bias_kernel(float* __restrict__ C, const float* __restrict__ b, int N) {
    int s = blockIdx.x;
    for (int c4 = threadIdx.x * 4; c4 < N; c4 += blockDim.x * 4) {
        float4 v = *(float4*)(C + (size_t)s * N + c4);
        float4 bb = *(const float4*)(b + c4);
        v.x += bb.x; v.y += bb.y; v.z += bb.z; v.w += bb.w;
        *(float4*)(C + (size_t)s * N + c4) = v;
    }
}

// ---------------------------------------------------------------------------
// Launch — fork/join overlap; 4-way attn/o-proj tail pipeline.
// ---------------------------------------------------------------------------
extern "C" void kernel_launch(void* const* d_in, const int* in_sizes, int n_in,
                              void* d_out, int out_size) {
    const float* hidden = (const float*)d_in[0];
    const float* q_w    = (const float*)d_in[2];
    const float* q_b    = (const float*)d_in[3];
    const float* kv_a_w = (const float*)d_in[4];
    const float* kv_b_w = (const float*)d_in[5];
    const float* o_w    = (const float*)d_in[6];
    const float* o_b    = (const float*)d_in[7];
    float* out = (float*)d_out;

    float  *p_q, *p_ckv, *p_kv;
    __half *p_ckvh, *p_qt, *p_kt, *p_vtT, *p_attn;
    __half *p_h, *p_qw, *p_kaw, *p_kbw, *p_ow;
    cudaGetSymbolAddress((void**)&p_q,    g_q);
    cudaGetSymbolAddress((void**)&p_ckv,  g_ckv);
    cudaGetSymbolAddress((void**)&p_ckvh, g_ckvh);
    cudaGetSymbolAddress((void**)&p_kv,   g_kv);
    cudaGetSymbolAddress((void**)&p_qt,   g_qt);
    cudaGetSymbolAddress((void**)&p_kt,   g_kt);
    cudaGetSymbolAddress((void**)&p_vtT,  g_vtT);
    cudaGetSymbolAddress((void**)&p_attn, g_attn);
    cudaGetSymbolAddress((void**)&p_h,    g_h);
    cudaGetSymbolAddress((void**)&p_qw,   g_qw);
    cudaGetSymbolAddress((void**)&p_kaw,  g_kaw);
    cudaGetSymbolAddress((void**)&p_kbw,  g_kbw);
    cudaGetSymbolAddress((void**)&p_ow,   g_ow);

    cudaFuncSetAttribute(wgemm_fp16,
                         cudaFuncAttributeMaxDynamicSharedMemorySize, GSMEM_BYTES);
    cudaFuncSetAttribute(attn_fp16,
                         cudaFuncAttributeMaxDynamicSharedMemorySize, ASMEM_BYTES);

    const int MB = SEQ / 128;
    const int OXB = (HDIM + 127) / 128;      // 23 col tiles for o-proj

    cudaStream_t s0 = 0;
    cudaStream_t skv, sow;
    cudaStreamCreateWithFlags(&skv, cudaStreamNonBlocking);
    cudaStreamCreateWithFlags(&sow, cudaStreamNonBlocking);
    cudaEvent_t eHid, eFork, eKv, eQw, eOw, eA3, eA2, eA1, eSide;
    cudaEventCreateWithFlags(&eHid,  cudaEventDisableTiming);
    cudaEventCreateWithFlags(&eFork, cudaEventDisableTiming);
    cudaEventCreateWithFlags(&eKv,   cudaEventDisableTiming);
    cudaEventCreateWithFlags(&eQw,   cudaEventDisableTiming);
    cudaEventCreateWithFlags(&eOw,   cudaEventDisableTiming);
    cudaEventCreateWithFlags(&eA3,   cudaEventDisableTiming);
    cudaEventCreateWithFlags(&eA2,   cudaEventDisableTiming);
    cudaEventCreateWithFlags(&eA1,   cudaEventDisableTiming);
    cudaEventCreateWithFlags(&eSide, cudaEventDisableTiming);

    auto roundH = [&](const float* src, __half* dst, int n, cudaStream_t st) {
        int n4 = n / 4;
        round_half_kernel<<<(n4 + 255) / 256, 256, 0, st>>>(src, dst, n4);
    };

    // fork: q_w + o_w roundings on side stream (independent of hidden)
    cudaEventRecord(eFork, s0);
    cudaStreamWaitEvent(sow, eFork, 0);
    roundH(q_w, p_qw, QDIM * HDIM, sow);
    cudaEventRecord(eQw, sow);
    roundH(o_w, p_ow, HDIM * QDIM, sow);
    cudaEventRecord(eOw, sow);

    // main: hidden rounding
    roundH(hidden, p_h, SEQ * HDIM, s0);
    cudaEventRecord(eHid, s0);
    cudaStreamWaitEvent(skv, eHid, 0);

    // kv chain (skv)
    roundH(kv_a_w, p_kaw, RANK * HDIM, skv);
    // q projection (main)
    cudaStreamWaitEvent(s0, eQw, 0);
    wgemm_fp16<<<dim3(QDIM / 128, MB), 256, GSMEM_BYTES, s0>>>(
        p_h, p_qw, p_q, SEQ, QDIM, HDIM);
    // kv chain continues
    wgemm_fp16<<<dim3(RANK / 128, MB), 256, GSMEM_BYTES, skv>>>(
        p_h, p_kaw, p_ckv, SEQ, RANK, HDIM);
    roundH(p_ckv, p_ckvh, SEQ * RANK, skv);
    roundH(kv_b_w, p_kbw, KVDIM * RANK, skv);
    wgemm_fp16<<<dim3(KVDIM / 128, MB), 256, GSMEM_BYTES, skv>>>(
        p_ckvh, p_kbw, p_kv, SEQ, KVDIM, RANK);
    rope_kv_kernel<<<dim3(SEQ / 64, NKV), 256, 0, skv>>>(p_kv, p_kt, p_vtT);
    cudaEventRecord(eKv, skv);

    // main: rope q
    rope_q_kernel<<<dim3(SEQ, NH / 4), 256, 0, s0>>>(p_q, q_b, p_qt);

    // join kv + o_w chains before attention / o-proj
    cudaStreamWaitEvent(s0, eKv, 0);
    cudaStreamWaitEvent(s0, eOw, 0);

    // --- 4-way attention + pipelined o-proj (descending work quarters) ---
    // Q3: qb 12..15 (rows 1536..2047), Q2: 8..11, Q1: 4..7, Q0: 0..3
    attn_fp16<<<dim3(4, NH), 256, ASMEM_BYTES, s0>>>(p_qt, p_kt, p_vtT, p_attn, 12);
    cudaEventRecord(eA3, s0);
    attn_fp16<<<dim3(4, NH), 256, ASMEM_BYTES, s0>>>(p_qt, p_kt, p_vtT, p_attn, 8);
    cudaEventRecord(eA2, s0);
    attn_fp16<<<dim3(4, NH), 256, ASMEM_BYTES, s0>>>(p_qt, p_kt, p_vtT, p_attn, 4);
    cudaEventRecord(eA1, s0);
    attn_fp16<<<dim3(4, NH), 256, ASMEM_BYTES, s0>>>(p_qt, p_kt, p_vtT, p_attn, 0);

    // side stream: o-proj for Q3, Q2, Q1 as they become ready, then their bias
    cudaStreamWaitEvent(sow, eA3, 0);
    wgemm_fp16<<<dim3(OXB, 4), 256, GSMEM_BYTES, sow>>>(
        p_attn + (size_t)1536 * QDIM, p_ow, out + (size_t)1536 * HDIM,
        512, HDIM, QDIM);
    cudaStreamWaitEvent(sow, eA2, 0);
    wgemm_fp16<<<dim3(OXB, 4), 256, GSMEM_BYTES, sow>>>(
        p_attn + (size_t)1024 * QDIM, p_ow, out + (size_t)1024 * HDIM,
        512, HDIM, QDIM);
    cudaStreamWaitEvent(sow, eA1, 0);
    wgemm_fp16<<<dim3(OXB, 4), 256, GSMEM_BYTES, sow>>>(
        p_attn + (size_t)512 * QDIM, p_ow, out + (size_t)512 * HDIM,
        512, HDIM, QDIM);
    add_bias_kernel<<<1536, 256, 0, sow>>>(out + (size_t)512 * HDIM, o_b, HDIM);
    cudaEventRecord(eSide, sow);

    // main: o-proj Q0 + its bias, then join side stream
    wgemm_fp16<<<dim3(OXB, 4), 256, GSMEM_BYTES, s0>>>(
        p_attn, p_ow, out, 512, HDIM, QDIM);
    add_bias_kernel<<<512, 256, 0, s0>>>(out, o_b, HDIM);
    cudaStreamWaitEvent(s0, eSide, 0);

    cudaStreamDestroy(skv);
    cudaStreamDestroy(sow);
    cudaEventDestroy(eHid);
    cudaEventDestroy(eFork);
    cudaEventDestroy(eKv);
    cudaEventDestroy(eQw);
    cudaEventDestroy(eOw);
    cudaEventDestroy(eA3);
    cudaEventDestroy(eA2);
    cudaEventDestroy(eA1);
    cudaEventDestroy(eSide);
}

// round 17
// speedup vs baseline: 1.1058x; 1.1058x over previous
#include <cuda_runtime.h>
#include <cuda_fp16.h>
#include <mma.h>
#include <cstdint>

using namespace nvcuda;

// Problem constants
#define SEQ   2048
#define HDIM  2880
#define NH    64
#define HD    64
#define NKV   8
#define RANK  384
#define QDIM  4096   // NH*HD
#define KVDIM 1024   // NKV*HD*2
#define ROPE_BASE 150000.0f

// ---------------------------------------------------------------------------
// Scratch
// ---------------------------------------------------------------------------
__device__ float  g_q   [SEQ * QDIM];
__device__ float  g_ckv [SEQ * RANK];
__device__ __half g_ckvh[SEQ * RANK];
__device__ float  g_kv  [SEQ * KVDIM];
__device__ __half g_qt  [NH  * SEQ * HD];
__device__ __half g_kt  [NKV * SEQ * HD];
__device__ __half g_vtT [NKV * HD * SEQ];
__device__ __half g_attn[SEQ * QDIM];
__device__ __half g_h   [SEQ * HDIM];
__device__ __half g_qw  [QDIM * HDIM];
__device__ __half g_kaw [RANK * HDIM];
__device__ __half g_kbw [KVDIM * RANK];
__device__ __half g_ow  [HDIM * QDIM];

__device__ __forceinline__ uint32_t smem_u32(const void* p) {
    uint32_t a;
    asm("{ .reg .u64 t; cvta.to.shared.u64 t, %1; cvt.u32.u64 %0, t; }"
        : "=r"(a) : "l"(p));
    return a;
}
__device__ __forceinline__ void cp_async16(uint32_t dst, const void* src) {
    asm volatile("cp.async.ca.shared.global [%0], [%1], 16;"
                 :: "r"(dst), "l"(src) : "memory");
}
__device__ __forceinline__ void cp_async_commit() {
    asm volatile("cp.async.commit_group;" ::: "memory");
}
__device__ __forceinline__ void cp_async_wait1() {
    asm volatile("cp.async.wait_group 1;" ::: "memory");
}
__device__ __forceinline__ void cp_async_wait0() {
    asm volatile("cp.async.wait_group 0;" ::: "memory");
}
__device__ __forceinline__ uint32_t pack_h2(float x, float y) {
    __half2 h = __float22half2_rn(make_float2(x, y));
    return *reinterpret_cast<uint32_t*>(&h);
}

// mma.sync m16n8k16 fp16 -> f32 accum
__device__ __forceinline__ void mma_f16(float d[4], const uint32_t a[4],
                                        const uint32_t b[2]) {
    asm volatile(
        "mma.sync.aligned.m16n8k16.row.col.f32.f16.f16.f32 "
        "{%0,%1,%2,%3},{%4,%5,%6,%7},{%8,%9},{%0,%1,%2,%3};"
        : "+f"(d[0]), "+f"(d[1]), "+f"(d[2]), "+f"(d[3])
        : "r"(a[0]), "r"(a[1]), "r"(a[2]), "r"(a[3]),
          "r"(b[0]), "r"(b[1]));
}

// ---------------------------------------------------------------------------
// Elementwise fp16 rounding pass
// ---------------------------------------------------------------------------
__global__ void round_half_kernel(const float* __restrict__ in,
                                  __half* __restrict__ out, int n4) {
    int i = blockIdx.x * blockDim.x + threadIdx.x;
    if (i < n4) {
        float4 v = ((const float4*)in)[i];
        uint2 u;
        u.x = pack_h2(v.x, v.y);
        u.y = pack_h2(v.z, v.w);
        ((uint2*)out)[i] = u;
    }
}

// ---------------------------------------------------------------------------
// Pipelined FP16 wmma GEMM: C = A @ B^T, f32 out. (R11 winner)
// CTA tile 128x128, BK=32, 3-stage cp.async, 8 warps, warp tile 64x32, 2 CTAs/SM.
// ---------------------------------------------------------------------------
#define GLDT 40
#define GST_A (128 * GLDT)
#define GST_HALVES ((128 + 128) * GLDT)
#define GSTAGES 3
#define GSMEM_BYTES (GSTAGES * GST_HALVES * 2)   // 61440

__global__ __launch_bounds__(256, 2)
void wgemm_fp16(const __half* __restrict__ A, const __half* __restrict__ B,
                float* __restrict__ C, int M, int N, int K) {
    extern __shared__ __half smh[];
    const int tid  = threadIdx.x;
    const int warp = tid >> 5;
    const int wm   = warp >> 2;
    const int wn   = warp & 3;
    const int row0 = blockIdx.y * 128;
    const int col0 = blockIdx.x * 128;
    const int NC   = K >> 5;

    wmma::fragment<wmma::accumulator, 16, 16, 16, float> acc[4][2];
#pragma unroll
    for (int i = 0; i < 4; i++)
#pragma unroll
        for (int j = 0; j < 2; j++) wmma::fill_fragment(acc[i][j], 0.0f);

    auto issue = [&](int c) {
        __half* sa = smh + (c % GSTAGES) * GST_HALVES;
        __half* sb = sa + GST_A;
        const int k0 = c << 5;
#pragma unroll
        for (int i = 0; i < 2; i++) {
            int idx = tid + i * 256;
            int r = idx >> 2, c8 = (idx & 3) * 8;
            cp_async16(smem_u32(sa + r * GLDT + c8),
                       A + (size_t)(row0 + r) * K + k0 + c8);
        }
#pragma unroll
        for (int i = 0; i < 2; i++) {
            int idx = tid + i * 256;
            int r = idx >> 2, c8 = (idx & 3) * 8;
            int gn = col0 + r; if (gn >= N) gn = N - 1;
            cp_async16(smem_u32(sb + r * GLDT + c8),
                       B + (size_t)gn * K + k0 + c8);
        }
    };

#pragma unroll
    for (int s = 0; s < GSTAGES - 1; s++) {
        issue(s);
        cp_async_commit();
    }

    for (int c = 0; c < NC; c++) {
        cp_async_wait1();
        __syncthreads();
        if (c + GSTAGES - 1 < NC) issue(c + GSTAGES - 1);
        cp_async_commit();

        __half* sa = smh + (c % GSTAGES) * GST_HALVES;
        __half* sb = sa + GST_A;
#pragma unroll
        for (int kk = 0; kk < 32; kk += 16) {
            wmma::fragment<wmma::matrix_a, 16, 16, 16, __half, wmma::row_major> af[4];
            wmma::fragment<wmma::matrix_b, 16, 16, 16, __half, wmma::col_major> bf[2];
#pragma unroll
            for (int i = 0; i < 4; i++)
                wmma::load_matrix_sync(af[i], sa + (wm * 64 + i * 16) * GLDT + kk, GLDT);
#pragma unroll
            for (int j = 0; j < 2; j++)
                wmma::load_matrix_sync(bf[j], sb + (wn * 32 + j * 16) * GLDT + kk, GLDT);
#pragma unroll
            for (int i = 0; i < 4; i++)
#pragma unroll
                for (int j = 0; j < 2; j++)
                    wmma::mma_sync(acc[i][j], af[i], bf[j], acc[i][j]);
        }
        __syncthreads();
    }

#pragma unroll
    for (int i = 0; i < 4; i++) {
        int gm = row0 + wm * 64 + i * 16;
#pragma unroll
        for (int j = 0; j < 2; j++) {
            int gn = col0 + wn * 32 + j * 16;
            if (gn < N)
                wmma::store_matrix_sync(C + (size_t)gm * N + gn, acc[i][j], N,
                                        wmma::mem_row_major);
        }
    }
}

// ---------------------------------------------------------------------------
// RoPE — fp16 outputs
// ---------------------------------------------------------------------------
__device__ __forceinline__ void rope_cs(int s, int d, float& c, float& sn) {
    int dd = d & 31;
    float inv = 1.0f / powf(ROPE_BASE, (float)(2 * dd) / 64.0f);
    float ang = (float)s * inv;
    c = cosf(ang);
    sn = sinf(ang);
}

__global__ void rope_q_kernel(const float* __restrict__ q, const float* __restrict__ qb,
                              __half* __restrict__ qt) {
    int s = blockIdx.x;
    int t = threadIdx.x;
    int h = blockIdx.y * 4 + (t >> 6);
    int d = t & 63;
    const float* row = q + (size_t)s * QDIM + h * HD;
    const float* brow = qb + h * HD;
    float v = row[d] + brow[d];
    float other = (d < 32) ? -(row[d + 32] + brow[d + 32]) : (row[d - 32] + brow[d - 32]);
    float c, sn; rope_cs(s, d, c, sn);
    qt[((size_t)h * SEQ + s) * HD + d] = __float2half_rn(v * c + other * sn);
}

__global__ void rope_kv_kernel(const float* __restrict__ kv,
                               __half* __restrict__ kt, __half* __restrict__ vtT) {
    __shared__ float vs[64][65];
    const int s0 = blockIdx.x * 64;
    const int kh = blockIdx.y;
    const int tid = threadIdx.x;

#pragma unroll
    for (int it = 0; it < 16; it++) {
        int r = it * 4 + (tid >> 6);
        int d = tid & 63;
        int s = s0 + r;
        const float* row = kv + (size_t)s * KVDIM + kh * (2 * HD);
        float kval = row[d];
        float other = (d < 32) ? -row[d + 32] : row[d - 32];
        float c, sn; rope_cs(s, d, c, sn);
        kt[((size_t)kh * SEQ + s) * HD + d] = __float2half_rn(kval * c + other * sn);
        vs[r][d] = row[HD + d];
    }
    __syncthreads();
#pragma unroll
    for (int it = 0; it < 16; it++) {
        int d = it * 4 + (tid >> 6);
        int cc = tid & 63;
        vtT[((size_t)kh * HD + d) * SEQ + s0 + cc] = __float2half_rn(vs[cc][d]);
    }
}

// ---------------------------------------------------------------------------
// Flash attention fp16 (R11 core + qb0 offset).
// Block = (head, 128 q rows at qb0+...), 8 warps; warp owns 16 rows.
// ---------------------------------------------------------------------------
#define KLD 72
#define ABUF (2 * 64 * KLD)
#define ASMEM_BYTES (2 * ABUF * 2)          // 36864

__global__ __launch_bounds__(256, 2)
void attn_fp16(const __half* __restrict__ qt, const __half* __restrict__ kt,
               const __half* __restrict__ vtT, __half* __restrict__ out, int qb0) {
    extern __shared__ __half smh[];
    const int tid  = threadIdx.x;
    const int warp = tid >> 5;
    const int lane = tid & 31;
    const int gid  = lane >> 2;
    const int q4   = lane & 3;
    const int h    = blockIdx.y;
    const int qb   = qb0 + gridDim.x - 1 - blockIdx.x;
    const int kvh  = h >> 3;

    const __half* Qg = qt + ((size_t)h * SEQ + qb * 128) * HD;
    const __half* Kg = kt + (size_t)kvh * SEQ * HD;
    const __half* Vg = vtT + (size_t)kvh * HD * SEQ;

#pragma unroll
    for (int i = 0; i < 4; i++) {
        int idx = tid + i * 256;
        int r = idx >> 3, c8 = (idx & 7) * 8;
        cp_async16(smem_u32(smh + r * KLD + c8), Qg + r * 64 + c8);
    }
    cp_async_commit();
    cp_async_wait0();
    __syncthreads();

    uint32_t qa[4][4];
    {
        const __half* qrow = smh + (warp * 16 + gid) * KLD;
#pragma unroll
        for (int kk = 0; kk < 4; kk++) {
            qa[kk][0] = *(const uint32_t*)&qrow[kk * 16 + 2 * q4];
            qa[kk][1] = *(const uint32_t*)&qrow[8 * KLD + kk * 16 + 2 * q4];
            qa[kk][2] = *(const uint32_t*)&qrow[kk * 16 + 8 + 2 * q4];
            qa[kk][3] = *(const uint32_t*)&qrow[8 * KLD + kk * 16 + 8 + 2 * q4];
        }
    }
    __syncthreads();

    auto issue_kv = [&](int jt, int buf) {
        __half* kb = smh + buf * ABUF;
        __half* vb = kb + 64 * KLD;
#pragma unroll
        for (int i = 0; i < 2; i++) {
            int idx = tid + i * 256;
            int r = idx >> 3, c8 = (idx & 7) * 8;
            cp_async16(smem_u32(kb + r * KLD + c8),
                       Kg + ((size_t)jt * 64 + r) * 64 + c8);
            cp_async16(smem_u32(vb + r * KLD + c8),
                       Vg + (size_t)r * SEQ + jt * 64 + c8);
        }
    };

    issue_kv(0, 0);
    cp_async_commit();

    const int ntiles = 2 * qb + 2;
    const int i0     = qb * 128 + warp * 16 + gid;
    const int iwmax  = qb * 128 + warp * 16 + 15;

    float m0 = -3.0e38f, m1 = -3.0e38f, l0 = 0.f, l1 = 0.f;
    float O[8][4];
#pragma unroll
    for (int t = 0; t < 8; t++)
#pragma unroll
        for (int e = 0; e < 4; e++) O[t][e] = 0.f;

    const uint32_t FULL = 0xffffffffu;

    for (int jt = 0; jt < ntiles; jt++) {
        const int buf = jt & 1;
        if (jt + 1 < ntiles) issue_kv(jt + 1, buf ^ 1);
        cp_async_commit();
        cp_async_wait1();
        __syncthreads();

        if (jt * 64 <= iwmax) {
            const __half* Kb = smh + buf * ABUF;
            const __half* Vb = Kb + 64 * KLD;

            float st[8][4];
#pragma unroll
            for (int t = 0; t < 8; t++)
#pragma unroll
                for (int e = 0; e < 4; e++) st[t][e] = 0.f;

#pragma unroll
            for (int kk = 0; kk < 4; kk++) {
#pragma unroll
                for (int t = 0; t < 8; t++) {
                    const __half* kp = Kb + (t * 8 + gid) * KLD + kk * 16 + 2 * q4;
                    uint32_t b[2] = { *(const uint32_t*)kp, *(const uint32_t*)(kp + 8) };
                    mma_f16(st[t], qa[kk], b);
                }
            }

            float mx0 = -3.0e38f, mx1 = -3.0e38f;
            const int jb2 = jt * 64 + 2 * q4;
#pragma unroll
            for (int t = 0; t < 8; t++) {
#pragma unroll
                for (int e = 0; e < 2; e++) {
                    int j = jb2 + t * 8 + e;
                    float v0 = st[t][e] * 0.125f;
                    float v1 = st[t][2 + e] * 0.125f;
                    if (j > i0)     v0 = -3.0e38f;
                    if (j > i0 + 8) v1 = -3.0e38f;
                    st[t][e] = v0; st[t][2 + e] = v1;
                    mx0 = fmaxf(mx0, v0); mx1 = fmaxf(mx1, v1);
                }
            }
            mx0 = fmaxf(mx0, __shfl_xor_sync(FULL, mx0, 1));
            mx0 = fmaxf(mx0, __shfl_xor_sync(FULL, mx0, 2));
            mx1 = fmaxf(mx1, __shfl_xor_sync(FULL, mx1, 1));
            mx1 = fmaxf(mx1, __shfl_xor_sync(FULL, mx1, 2));

            float mn0 = fmaxf(m0, mx0), mn1 = fmaxf(m1, mx1);
            float sc0 = __expf(m0 - mn0), sc1 = __expf(m1 - mn1);
            m0 = mn0; m1 = mn1;

            float rs0 = 0.f, rs1 = 0.f;
#pragma unroll
            for (int t = 0; t < 8; t++) {
#pragma unroll
                for (int e = 0; e < 2; e++) {
                    float p0 = __expf(st[t][e]     - m0);
                    float p1 = __expf(st[t][2 + e] - m1);
                    st[t][e] = p0; st[t][2 + e] = p1;
                    rs0 += p0; rs1 += p1;
                }
            }
            rs0 += __shfl_xor_sync(FULL, rs0, 1);
            rs0 += __shfl_xor_sync(FULL, rs0, 2);
            rs1 += __shfl_xor_sync(FULL, rs1, 1);
            rs1 += __shfl_xor_sync(FULL, rs1, 2);
            l0 = l0 * sc0 + rs0;
            l1 = l1 * sc1 + rs1;

#pragma unroll
            for (int t = 0; t < 8; t++) {
                O[t][0] *= sc0; O[t][1] *= sc0;
                O[t][2] *= sc1; O[t][3] *= sc1;
            }

            uint32_t pa[4][4];
#pragma unroll
            for (int kk = 0; kk < 4; kk++) {
                pa[kk][0] = pack_h2(st[2 * kk][0],     st[2 * kk][1]);
                pa[kk][1] = pack_h2(st[2 * kk][2],     st[2 * kk][3]);
                pa[kk][2] = pack_h2(st[2 * kk + 1][0], st[2 * kk + 1][1]);
                pa[kk][3] = pack_h2(st[2 * kk + 1][2], st[2 * kk + 1][3]);
            }

#pragma unroll
            for (int kk = 0; kk < 4; kk++) {
#pragma unroll
                for (int t = 0; t < 8; t++) {
                    const __half* vp = Vb + (t * 8 + gid) * KLD + kk * 16 + 2 * q4;
                    uint32_t b[2] = { *(const uint32_t*)vp, *(const uint32_t*)(vp + 8) };
                    mma_f16(O[t], pa[kk], b);
                }
            }
        }
        __syncthreads();
    }

    float inv0 = 1.0f / l0, inv1 = 1.0f / l1;
    const int r0 = qb * 128 + warp * 16 + gid;
    __half* dst0 = out + (size_t)r0 * QDIM + h * HD;
    __half* dst1 = dst0 + (size_t)8 * QDIM;
#pragma unroll
    for (int t = 0; t < 8; t++) {
        uint32_t v0 = pack_h2(O[t][0] * inv0, O[t][1] * inv0);
        uint32_t v1 = pack_h2(O[t][2] * inv1, O[t][3] * inv1);
        *(uint32_t*)(dst0 + t * 8 + 2 * q4) = v0;
        *(uint32_t*)(dst1 + t * 8 + 2 * q4) = v1;
    }
}

// ---------------------------------------------------------------------------
// Bias add (row range via pointer offset)
// ---------------------------------------------------------------------------
__global__ void add_bias_kernel(float* __restrict__ C, const float* __restrict__ b, int N) {
    int s = blockIdx.x;
    for (int c4 = threadIdx.x * 4; c4 < N; c4 += blockDim.x * 4) {
        float4 v = *(float4*)(C + (size_t)s * N + c4);
        float4 bb = *(const float4*)(b + c4);
        v.x += bb.x; v.y += bb.y; v.z += bb.z; v.w += bb.w;
        *(float4*)(C + (size_t)s * N + c4) = v;
    }
}

// ---------------------------------------------------------------------------
// Launch — R13 best config: fork/join overlap + 2-way attn/o-proj split.
// Bias for the high half rides the side stream (hidden under o-proj_lo).
// ---------------------------------------------------------------------------
extern "C" void kernel_launch(void* const* d_in, const int* in_sizes, int n_in,
                              void* d_out, int out_size) {
    const float* hidden = (const float*)d_in[0];
    const float* q_w    = (const float*)d_in[2];
    const float* q_b    = (const float*)d_in[3];
    const float* kv_a_w = (const float*)d_in[4];
    const float* kv_b_w = (const float*)d_in[5];
    const float* o_w    = (const float*)d_in[6];
    const float* o_b    = (const float*)d_in[7];
    float* out = (float*)d_out;

    float  *p_q, *p_ckv, *p_kv;
    __half *p_ckvh, *p_qt, *p_kt, *p_vtT, *p_attn;
    __half *p_h, *p_qw, *p_kaw, *p_kbw, *p_ow;
    cudaGetSymbolAddress((void**)&p_q,    g_q);
    cudaGetSymbolAddress((void**)&p_ckv,  g_ckv);
    cudaGetSymbolAddress((void**)&p_ckvh, g_ckvh);
    cudaGetSymbolAddress((void**)&p_kv,   g_kv);
    cudaGetSymbolAddress((void**)&p_qt,   g_qt);
    cudaGetSymbolAddress((void**)&p_kt,   g_kt);
    cudaGetSymbolAddress((void**)&p_vtT,  g_vtT);
    cudaGetSymbolAddress((void**)&p_attn, g_attn);
    cudaGetSymbolAddress((void**)&p_h,    g_h);
    cudaGetSymbolAddress((void**)&p_qw,   g_qw);
    cudaGetSymbolAddress((void**)&p_kaw,  g_kaw);
    cudaGetSymbolAddress((void**)&p_kbw,  g_kbw);
    cudaGetSymbolAddress((void**)&p_ow,   g_ow);

    cudaFuncSetAttribute(wgemm_fp16,
                         cudaFuncAttributeMaxDynamicSharedMemorySize, GSMEM_BYTES);
    cudaFuncSetAttribute(attn_fp16,
                         cudaFuncAttributeMaxDynamicSharedMemorySize, ASMEM_BYTES);

    const int MB = SEQ / 128;

    cudaStream_t s0 = 0;
    cudaStream_t skv, sow;
    cudaStreamCreateWithFlags(&skv, cudaStreamNonBlocking);
    cudaStreamCreateWithFlags(&sow, cudaStreamNonBlocking);
    cudaEvent_t eHid, eFork, eKv, eOw, eAhi, eOhi;
    cudaEventCreateWithFlags(&eHid,  cudaEventDisableTiming);
    cudaEventCreateWithFlags(&eFork, cudaEventDisableTiming);
    cudaEventCreateWithFlags(&eKv,   cudaEventDisableTiming);
    cudaEventCreateWithFlags(&eOw,   cudaEventDisableTiming);
    cudaEventCreateWithFlags(&eAhi,  cudaEventDisableTiming);
    cudaEventCreateWithFlags(&eOhi,  cudaEventDisableTiming);

    auto roundH = [&](const float* src, __half* dst, int n, cudaStream_t st) {
        int n4 = n / 4;
        round_half_kernel<<<(n4 + 255) / 256, 256, 0, st>>>(src, dst, n4);
    };

    // --- fork: o_w rounding fully independent ---
    cudaEventRecord(eFork, s0);
    cudaStreamWaitEvent(sow, eFork, 0);
    roundH(o_w, p_ow, HDIM * QDIM, sow);
    cudaEventRecord(eOw, sow);

    // main: hidden rounding (both chains need it)
    roundH(hidden, p_h, SEQ * HDIM, s0);
    cudaEventRecord(eHid, s0);
    cudaStreamWaitEvent(skv, eHid, 0);

    // q chain (main)
    roundH(q_w, p_qw, QDIM * HDIM, s0);
    // kv chain (skv)
    roundH(kv_a_w, p_kaw, RANK * HDIM, skv);
    // q projection (main)
    wgemm_fp16<<<dim3(QDIM / 128, MB), 256, GSMEM_BYTES, s0>>>(
        p_h, p_qw, p_q, SEQ, QDIM, HDIM);
    // kv chain continues
    wgemm_fp16<<<dim3(RANK / 128, MB), 256, GSMEM_BYTES, skv>>>(
        p_h, p_kaw, p_ckv, SEQ, RANK, HDIM);
    roundH(p_ckv, p_ckvh, SEQ * RANK, skv);
    roundH(kv_b_w, p_kbw, KVDIM * RANK, skv);
    wgemm_fp16<<<dim3(KVDIM / 128, MB), 256, GSMEM_BYTES, skv>>>(
        p_ckvh, p_kbw, p_kv, SEQ, KVDIM, RANK);
    rope_kv_kernel<<<dim3(SEQ / 64, NKV), 256, 0, skv>>>(p_kv, p_kt, p_vtT);
    cudaEventRecord(eKv, skv);

    // main: rope q
    rope_q_kernel<<<dim3(SEQ, NH / 4), 256, 0, s0>>>(p_q, q_b, p_qt);

    // join kv + o_w chains before attention / o-proj
    cudaStreamWaitEvent(s0, eKv, 0);
    cudaStreamWaitEvent(s0, eOw, 0);

    // --- split attention + pipelined o-proj (2-way, full waves) ---
    const int HB = 8;                      // 8 q-blocks per half (1024 rows)
    attn_fp16<<<dim3(HB, NH), 256, ASMEM_BYTES, s0>>>(p_qt, p_kt, p_vtT, p_attn, HB);
    cudaEventRecord(eAhi, s0);
    cudaStreamWaitEvent(sow, eAhi, 0);
    wgemm_fp16<<<dim3((HDIM + 127) / 128, HB), 256, GSMEM_BYTES, sow>>>(
        p_attn + (size_t)1024 * QDIM, p_ow, out + (size_t)1024 * HDIM,
        1024, HDIM, QDIM);
    // high-half bias on the side stream (hidden under o-proj_lo)
    add_bias_kernel<<<1024, 256, 0, sow>>>(out + (size_t)1024 * HDIM, o_b, HDIM);
    cudaEventRecord(eOhi, sow);
    // attention low half + its o-proj on main
    attn_fp16<<<dim3(HB, NH), 256, ASMEM_BYTES, s0>>>(p_qt, p_kt, p_vtT, p_attn, 0);
    wgemm_fp16<<<dim3((HDIM + 127) / 128, HB), 256, GSMEM_BYTES, s0>>>(
        p_attn, p_ow, out, 1024, HDIM, QDIM);
    // low-half bias on main, then join
    add_bias_kernel<<<1024, 256, 0, s0>>>(out, o_b, HDIM);
    cudaStreamWaitEvent(s0, eOhi, 0);

    cudaStreamDestroy(skv);
    cudaStreamDestroy(sow);
    cudaEventDestroy(eHid);
    cudaEventDestroy(eFork);
    cudaEventDestroy(eKv);
    cudaEventDestroy(eOw);
    cudaEventDestroy(eAhi);
    cudaEventDestroy(eOhi);
}